// round 1
// baseline (speedup 1.0000x reference)
#include <cuda_runtime.h>
#include <cuda_bf16.h>
#include <cstdint>
#include <math.h>

#define N_IN   256
#define N_OUT  64
#define TM     128   // rows per GEMM block
#define KC     32    // k-chunk

// Scratch for h = x@W + b  (100000 x 64 floats = 25.6 MB)
__device__ float g_h[100000 * N_OUT];

// ---------------------------------------------------------------------------
// zero the output accumulator (d_out is poisoned with 0xAA by the harness)
// ---------------------------------------------------------------------------
__global__ void zero_kernel(float4* __restrict__ out, int n4) {
    int i = blockIdx.x * blockDim.x + threadIdx.x;
    if (i < n4) out[i] = make_float4(0.f, 0.f, 0.f, 0.f);
}

// ---------------------------------------------------------------------------
// GEMM: h[N, 64] = x[N, 256] @ W[256, 64] + b[64]
// Block: 256 threads, 128 rows x 64 cols. Thread: 8 rows x 4 cols register tile.
// ---------------------------------------------------------------------------
__global__ void __launch_bounds__(256) gemm_kernel(
    const float* __restrict__ x, const float* __restrict__ W,
    const float* __restrict__ b, int N)
{
    __shared__ float xs[TM][KC];      // 16 KB
    __shared__ float ws[KC][N_OUT];   // 8 KB

    const int tid = threadIdx.x;
    const int block_row = blockIdx.x * TM;
    const int tx = tid & 15;          // col group: cols tx*4 .. tx*4+3
    const int ty = tid >> 4;          // row group: rows ty*8 .. ty*8+7

    float acc[8][4];
#pragma unroll
    for (int r = 0; r < 8; r++)
#pragma unroll
        for (int c = 0; c < 4; c++) acc[r][c] = 0.f;

    for (int k0 = 0; k0 < N_IN; k0 += KC) {
        // load x tile: 128 rows x 32 k  (1024 float4, 4 per thread)
        {
            const int k4 = (tid & 7) * 4;   // 8 float4 per row
            const int r0 = tid >> 3;        // 32 rows per pass
#pragma unroll
            for (int p = 0; p < 4; p++) {
                const int r = r0 + p * 32;
                const int grow = block_row + r;
                float4 v = make_float4(0.f, 0.f, 0.f, 0.f);
                if (grow < N)
                    v = *(const float4*)(x + (size_t)grow * N_IN + k0 + k4);
                *(float4*)&xs[r][k4] = v;
            }
        }
        // load W tile: 32 k x 64 cols (512 float4, 2 per thread)
        {
            const int c4 = (tid & 15) * 4;
            const int kk = tid >> 4;        // 16 k per pass
#pragma unroll
            for (int p = 0; p < 2; p++) {
                const int k = kk + p * 16;
                *(float4*)&ws[k][c4] =
                    *(const float4*)(W + (size_t)(k0 + k) * N_OUT + c4);
            }
        }
        __syncthreads();

#pragma unroll
        for (int k = 0; k < KC; k++) {
            const float4 wq = *(const float4*)&ws[k][tx * 4];
#pragma unroll
            for (int r = 0; r < 8; r++) {
                const float xv = xs[ty * 8 + r][k];
                acc[r][0] += xv * wq.x;
                acc[r][1] += xv * wq.y;
                acc[r][2] += xv * wq.z;
                acc[r][3] += xv * wq.w;
            }
        }
        __syncthreads();
    }

    const float4 bb = *(const float4*)(b + tx * 4);
#pragma unroll
    for (int r = 0; r < 8; r++) {
        const int grow = block_row + ty * 8 + r;
        if (grow < N) {
            float4 o = make_float4(acc[r][0] + bb.x, acc[r][1] + bb.y,
                                   acc[r][2] + bb.z, acc[r][3] + bb.w);
            *(float4*)(g_h + (size_t)grow * N_OUT + tx * 4) = o;
        }
    }
}

// ---------------------------------------------------------------------------
// Edge scatter: out[row] += val * h[col], one half-warp (16 lanes) per edge,
// each lane owns one float4 slice of the 64-wide feature. Vector RED (no
// return) keeps the L2 atomic op count at 16 per edge instead of 64.
// ---------------------------------------------------------------------------
__global__ void __launch_bounds__(256) scatter_kernel(
    const int* __restrict__ rows, const int* __restrict__ cols,
    const float* __restrict__ vals, float* __restrict__ out, int E)
{
    const int gtid = blockIdx.x * blockDim.x + threadIdx.x;
    const int e    = gtid >> 4;
    const int lane = gtid & 15;
    if (e >= E) return;

    const int   r = rows[e];
    const int   c = cols[e];
    const float v = vals[e];

    float4 m = *((const float4*)(g_h + (size_t)c * N_OUT) + lane);
    m.x *= v; m.y *= v; m.z *= v; m.w *= v;

    float* o = out + (size_t)r * N_OUT + lane * 4;
    asm volatile("red.global.add.v4.f32 [%0], {%1, %2, %3, %4};"
                 :: "l"(o), "f"(m.x), "f"(m.y), "f"(m.z), "f"(m.w)
                 : "memory");
}

// ---------------------------------------------------------------------------
// ELU epilogue (alpha = 1): x > 0 ? x : expm1(x)
// ---------------------------------------------------------------------------
__global__ void elu_kernel(float* __restrict__ out, int n) {
    int i = blockIdx.x * blockDim.x + threadIdx.x;
    if (i < n) {
        const float v = out[i];
        out[i] = v > 0.f ? v : expm1f(v);
    }
}

// ---------------------------------------------------------------------------
extern "C" void kernel_launch(void* const* d_in, const int* in_sizes, int n_in,
                              void* d_out, int out_size)
{
    const float* x  = (const float*)d_in[0];
    const int*   er = (const int*)  d_in[1];
    const int*   ec = (const int*)  d_in[2];
    const float* ev = (const float*)d_in[3];
    const float* W  = (const float*)d_in[4];
    const float* b  = (const float*)d_in[5];
    float* out = (float*)d_out;

    const int N = in_sizes[0] / N_IN;   // 100000
    const int E = in_sizes[1];          // 1600000
    const int n_out_elems = N * N_OUT;

    // 1) zero accumulator
    {
        int n4 = n_out_elems / 4;
        zero_kernel<<<(n4 + 255) / 256, 256>>>((float4*)out, n4);
    }
    // 2) h = x @ W + b
    gemm_kernel<<<(N + TM - 1) / TM, 256>>>(x, W, b, N);
    // 3) out[row] += val * h[col] over all edges (16 lanes per edge)
    {
        long long total = (long long)E * 16;
        int blocks = (int)((total + 255) / 256);
        scatter_kernel<<<blocks, 256>>>(er, ec, ev, out, E);
    }
    // 4) ELU in place
    elu_kernel<<<(n_out_elems + 255) / 256, 256>>>(out, n_out_elems);
}

// round 3
// speedup vs baseline: 1.2477x; 1.2477x over previous
#include <cuda_runtime.h>
#include <cuda_bf16.h>
#include <cstdint>
#include <math.h>

#define N_IN   256
#define N_OUT  64
#define TM     128            // rows per GEMM CTA
#define XS_STRIDE 68          // x tile smem stride (floats) — conflict-free A frags
#define WS_STRIDE 72          // W tile smem stride (floats) — conflict-free B frags

// Scratch for h = x@W + b  (100000 x 64 floats = 25.6 MB)
__device__ float g_h[100000 * N_OUT];

// dynamic smem: xs[128][68] + ws[256][72]
#define XS_FLOATS (128 * XS_STRIDE)
#define WS_FLOATS (256 * WS_STRIDE)
#define GEMM_SMEM ((XS_FLOATS + WS_FLOATS) * 4)   // 34816 + 73728 = 108544 B

__device__ __forceinline__ float to_tf32(float f) {
    uint32_t r;
    asm("cvt.rna.tf32.f32 %0, %1;" : "=r"(r) : "f"(f));
    return __uint_as_float(r);
}

// ===========================================================================
// zero the output accumulator (d_out is poisoned with 0xAA)
// ===========================================================================
__global__ void zero_kernel(float4* __restrict__ out, int n4) {
    int i = blockIdx.x * blockDim.x + threadIdx.x;
    if (i < n4) out[i] = make_float4(0.f, 0.f, 0.f, 0.f);
}

// ===========================================================================
// GEMM via mma.sync m16n8k8 tf32: h[N,64] = x[N,256] @ W[256,64] + b
// CTA: 256 threads = 8 warps; warp w owns rows [w*16, w*16+16), all 64 cols.
// W (256x64) staged once in smem; x staged in 4 chunks of 128x64.
// ===========================================================================
__global__ void __launch_bounds__(256) gemm_mma_kernel(
    const float* __restrict__ x, const float* __restrict__ W,
    const float* __restrict__ b, int N)
{
    extern __shared__ float smem[];
    float* xs = smem;                // [128][XS_STRIDE]
    float* ws = smem + XS_FLOATS;    // [256][WS_STRIDE]

    const int tid  = threadIdx.x;
    const int w    = tid >> 5;
    const int lane = tid & 31;
    const int g    = lane >> 2;      // group id 0..7
    const int tig  = lane & 3;       // thread-in-group 0..3
    const int block_row = blockIdx.x * TM;

    // ---- stage W (256x64) once, converted to tf32 ----
    for (int id = tid; id < 256 * 16; id += 256) {        // 4096 float4
        const int row = id >> 4;
        const int f4  = id & 15;
        float4 v = *(const float4*)(W + (size_t)row * N_OUT + f4 * 4);
        v.x = to_tf32(v.x); v.y = to_tf32(v.y);
        v.z = to_tf32(v.z); v.w = to_tf32(v.w);
        *(float4*)&ws[row * WS_STRIDE + f4 * 4] = v;      // 288B rows: 16B aligned
    }

    float acc[8][4];
#pragma unroll
    for (int nt = 0; nt < 8; nt++)
#pragma unroll
        for (int j = 0; j < 4; j++) acc[nt][j] = 0.f;

    for (int kc = 0; kc < 4; kc++) {
        // ---- stage x chunk 128 rows x 64 k (2048 float4, 8 per thread) ----
#pragma unroll
        for (int p = 0; p < 8; p++) {
            const int id  = tid + p * 256;
            const int row = id >> 4;
            const int f4  = id & 15;
            int grow = block_row + row;
            if (grow >= N) grow = N - 1;                  // clamp, result unused
            float4 v = *(const float4*)(x + (size_t)grow * N_IN + kc * 64 + f4 * 4);
            float* dst = &xs[row * XS_STRIDE + f4 * 4];
            dst[0] = to_tf32(v.x); dst[1] = to_tf32(v.y);
            dst[2] = to_tf32(v.z); dst[3] = to_tf32(v.w);
        }
        __syncthreads();

#pragma unroll
        for (int k8 = 0; k8 < 8; k8++) {
            const int kb = k8 * 8;
            // A fragment (rows w*16+g / +8, cols kb+tig / +4)
            const int r0 = (w * 16 + g) * XS_STRIDE;
            const int r1 = (w * 16 + g + 8) * XS_STRIDE;
            const uint32_t a0 = __float_as_uint(xs[r0 + kb + tig]);
            const uint32_t a1 = __float_as_uint(xs[r1 + kb + tig]);
            const uint32_t a2 = __float_as_uint(xs[r0 + kb + tig + 4]);
            const uint32_t a3 = __float_as_uint(xs[r1 + kb + tig + 4]);

            const int krow = kc * 64 + kb;
#pragma unroll
            for (int nt = 0; nt < 8; nt++) {
                const uint32_t b0 =
                    __float_as_uint(ws[(krow + tig) * WS_STRIDE + nt * 8 + g]);
                const uint32_t b1 =
                    __float_as_uint(ws[(krow + tig + 4) * WS_STRIDE + nt * 8 + g]);
                asm volatile(
                    "mma.sync.aligned.m16n8k8.row.col.f32.tf32.tf32.f32 "
                    "{%0, %1, %2, %3}, {%4, %5, %6, %7}, {%8, %9}, "
                    "{%0, %1, %2, %3};"
                    : "+f"(acc[nt][0]), "+f"(acc[nt][1]),
                      "+f"(acc[nt][2]), "+f"(acc[nt][3])
                    : "r"(a0), "r"(a1), "r"(a2), "r"(a3), "r"(b0), "r"(b1));
            }
        }
        __syncthreads();
    }

    // ---- epilogue: bias add, store to g_h ----
    const int row0 = block_row + w * 16 + g;
    const int row1 = row0 + 8;
#pragma unroll
    for (int nt = 0; nt < 8; nt++) {
        const int col = nt * 8 + 2 * tig;
        const float bx = b[col], by = b[col + 1];
        if (row0 < N) {
            float2 o = make_float2(acc[nt][0] + bx, acc[nt][1] + by);
            *(float2*)(g_h + (size_t)row0 * N_OUT + col) = o;
        }
        if (row1 < N) {
            float2 o = make_float2(acc[nt][2] + bx, acc[nt][3] + by);
            *(float2*)(g_h + (size_t)row1 * N_OUT + col) = o;
        }
    }
}

// ===========================================================================
// Edge scatter: out[row] += val * h[col]. 16 lanes per edge, one float4 slice
// per lane, red.global.add.v4.f32 (no return).
// ===========================================================================
__global__ void __launch_bounds__(256) scatter_kernel(
    const int* __restrict__ rows, const int* __restrict__ cols,
    const float* __restrict__ vals, float* __restrict__ out, int E)
{
    const int gtid = blockIdx.x * blockDim.x + threadIdx.x;
    const int e    = gtid >> 4;
    const int lane = gtid & 15;
    if (e >= E) return;

    const int   r = rows[e];
    const int   c = cols[e];
    const float v = vals[e];

    float4 m = *((const float4*)(g_h + (size_t)c * N_OUT) + lane);
    m.x *= v; m.y *= v; m.z *= v; m.w *= v;

    float* o = out + (size_t)r * N_OUT + lane * 4;
    asm volatile("red.global.add.v4.f32 [%0], {%1, %2, %3, %4};"
                 :: "l"(o), "f"(m.x), "f"(m.y), "f"(m.z), "f"(m.w)
                 : "memory");
}

// ===========================================================================
// ELU epilogue, float4-vectorized
// ===========================================================================
__global__ void elu_kernel(float4* __restrict__ out, int n4) {
    int i = blockIdx.x * blockDim.x + threadIdx.x;
    if (i < n4) {
        float4 v = out[i];
        v.x = v.x > 0.f ? v.x : expm1f(v.x);
        v.y = v.y > 0.f ? v.y : expm1f(v.y);
        v.z = v.z > 0.f ? v.z : expm1f(v.z);
        v.w = v.w > 0.f ? v.w : expm1f(v.w);
        out[i] = v;
    }
}

// ===========================================================================
extern "C" void kernel_launch(void* const* d_in, const int* in_sizes, int n_in,
                              void* d_out, int out_size)
{
    const float* x  = (const float*)d_in[0];
    const int*   er = (const int*)  d_in[1];
    const int*   ec = (const int*)  d_in[2];
    const float* ev = (const float*)d_in[3];
    const float* W  = (const float*)d_in[4];
    const float* b  = (const float*)d_in[5];
    float* out = (float*)d_out;

    const int N = in_sizes[0] / N_IN;   // 100000
    const int E = in_sizes[1];          // 1600000
    const int n_out_elems = N * N_OUT;

    static bool attr_set = false;
    if (!attr_set) {
        cudaFuncSetAttribute(gemm_mma_kernel,
                             cudaFuncAttributeMaxDynamicSharedMemorySize, GEMM_SMEM);
        attr_set = true;
    }

    // 1) zero accumulator
    {
        int n4 = n_out_elems / 4;
        zero_kernel<<<(n4 + 255) / 256, 256>>>((float4*)out, n4);
    }
    // 2) h = x @ W + b  (mma.sync tf32)
    gemm_mma_kernel<<<(N + TM - 1) / TM, 256, GEMM_SMEM>>>(x, W, b, N);
    // 3) out[row] += val * h[col] over all edges
    {
        long long total = (long long)E * 16;
        int blocks = (int)((total + 255) / 256);
        scatter_kernel<<<blocks, 256>>>(er, ec, ev, out, E);
    }
    // 4) ELU in place (vectorized)
    elu_kernel<<<(n_out_elems / 4 + 255) / 256, 256>>>((float4*)out, n_out_elems / 4);
}